// round 11
// baseline (speedup 1.0000x reference)
#include <cuda_runtime.h>

// Fixed shapes: I(16,3,512,512), T(16,256), P(3,16), Q(16,3)
#define BS        16
#define CHANS     3
#define HW        (512 * 512)          // 262144 floats per channel
#define NCH       (BS * CHANS)         // 48 channels
#define CH4       65536                // float4 per channel
#define NBLOCKS   256                  // uniform flat slices, single wave @ occ 2
#define PB4       12288                // float4 per block (= TOTAL4 / 256)
#define THREADS   256
#define VPT       48                   // float4 per thread (6 batches of 8)
#define KDIM      16

// Deterministic scratch: each block owns slot pair (A,B); no atomics.
// A[bid] = partial for channel chA(bid) = (3*bid)>>4 ; B[bid] = for chA+1.
__device__ float g_pA[NBLOCKS];
__device__ float g_pB[NBLOCKS];

__global__ __launch_bounds__(THREADS)
void dncm_reduce_kernel(const float* __restrict__ I) {
    const int bid = blockIdx.x;              // 0..255
    const int t   = threadIdx.x;

    const int g0   = bid * PB4;              // first float4 group of this block
    const int chA  = (3 * bid) >> 4;         // == g0 >> 16
    const int bnd  = (chA + 1) << 16;        // first group of next channel

    const float4* __restrict__ base = reinterpret_cast<const float4*>(I) + g0;

    float s0 = 0.0f, s1 = 0.0f;
    // 6 batches of 8 independent float4 loads (front-batched MLP=8).
    #pragma unroll
    for (int batch = 0; batch < 6; batch++) {
        float4 v[8];
        int idx[8];
        #pragma unroll
        for (int i = 0; i < 8; i++) {
            idx[i] = batch * (8 * THREADS) + i * THREADS + t;  // < PB4
            v[i] = base[idx[i]];
        }
        #pragma unroll
        for (int i = 0; i < 8; i++) {
            const float e = (v[i].x + v[i].y) + (v[i].z + v[i].w);
            if (g0 + idx[i] < bnd) s0 += e; else s1 += e;
        }
    }

    // Reduce both accumulators across the block (fixed tree -> deterministic).
    #pragma unroll
    for (int off = 16; off > 0; off >>= 1) {
        s0 += __shfl_xor_sync(0xffffffffu, s0, off);
        s1 += __shfl_xor_sync(0xffffffffu, s1, off);
    }

    __shared__ float w0[THREADS / 32];
    __shared__ float w1[THREADS / 32];
    if ((t & 31) == 0) { w0[t >> 5] = s0; w1[t >> 5] = s1; }
    __syncthreads();

    if (t == 0) {
        float a = 0.0f, b = 0.0f;
        #pragma unroll
        for (int i = 0; i < THREADS / 32; i++) { a += w0[i]; b += w1[i]; }
        g_pA[bid] = a;
        g_pB[bid] = b;
        cudaTriggerProgrammaticLaunchCompletion();
    }
}

// Epilogue (PDL secondary): prefetch T/Q/P before gridDepSync, then gather the
// 2x256 slots into S[48]. 768 threads = 48 channel teams x 16 lanes; lane l of
// team c scans bids l, l+16, ..., l+240 with predicated adds (fixed order).
__global__ __launch_bounds__(768)
void dncm_final_kernel(const float* __restrict__ T,
                       const float* __restrict__ P,
                       const float* __restrict__ Q,
                       float* __restrict__ out) {
    const int t  = threadIdx.x;        // 0..767
    const int c  = t >> 4;             // channel team 0..47
    const int l  = t & 15;             // lane in team

    // ---- Prefetch phase (overlaps with primary tail) ----
    const int b = t >> 4;              // batch (valid for t < 256)
    const int k = t & 15;
    float4 t0, t1, t2, t3;
    float r[KDIM];
    float P0 = 0.f, P1 = 0.f, P2 = 0.f;
    if (t < 256) {
        const float4* __restrict__ Tv =
            reinterpret_cast<const float4*>(T + b * (KDIM * KDIM) + k * KDIM);
        t0 = Tv[0]; t1 = Tv[1]; t2 = Tv[2]; t3 = Tv[3];
        #pragma unroll
        for (int q = 0; q < KDIM; q++)
            r[q] = Q[q * 3 + 0] + Q[q * 3 + 1] + Q[q * 3 + 2];
        P0 = P[0 * KDIM + k];
        P1 = P[1 * KDIM + k];
        P2 = P[2 * KDIM + k];
    }

    cudaGridDependencySynchronize();

    // ---- Gather slots into per-channel sums ----
    float s = 0.0f;
    #pragma unroll
    for (int i = 0; i < NBLOCKS / 16; i++) {      // 16 bids per lane
        const int bid = l + i * 16;
        const int chA = (3 * bid) >> 4;
        const float a = g_pA[bid];
        const float bb = g_pB[bid];
        if (chA == c)     s += a;
        if (chA + 1 == c) s += bb;
    }
    #pragma unroll
    for (int off = 8; off > 0; off >>= 1)
        s += __shfl_xor_sync(0xffffffffu, s, off);

    __shared__ float S[NCH];
    if (l == 0) S[c] = s;
    __syncthreads();

    if (t < 256) {
        // A[b,k] = sum_c S[b,c] * P[c,k]
        const float A = S[b * CHANS + 0] * P0
                      + S[b * CHANS + 1] * P1
                      + S[b * CHANS + 2] * P2;

        // d = T_b[k,:] . r
        float d = t0.x * r[0]  + t0.y * r[1]  + t0.z * r[2]  + t0.w * r[3]
                + t1.x * r[4]  + t1.y * r[5]  + t1.z * r[6]  + t1.w * r[7]
                + t2.x * r[8]  + t2.y * r[9]  + t2.z * r[10] + t2.w * r[11]
                + t3.x * r[12] + t3.y * r[13] + t3.z * r[14] + t3.w * r[15];

        float val = d * A;
        #pragma unroll
        for (int off = 8; off > 0; off >>= 1)
            val += __shfl_xor_sync(0xffffffffu, val, off);

        if (k == 0)
            out[b] = val * (1.0f / (float)(HW * CHANS));
    }
}

extern "C" void kernel_launch(void* const* d_in, const int* in_sizes, int n_in,
                              void* d_out, int out_size) {
    const float* I = (const float*)d_in[0];   // (16,3,512,512)
    const float* T = (const float*)d_in[1];   // (16,256)
    const float* P = (const float*)d_in[2];   // (3,16)
    const float* Q = (const float*)d_in[3];   // (16,3)
    float* out = (float*)d_out;               // (16,1)

    dncm_reduce_kernel<<<NBLOCKS, THREADS>>>(I);

    cudaLaunchConfig_t cfg = {};
    cfg.gridDim  = dim3(1, 1, 1);
    cfg.blockDim = dim3(768, 1, 1);
    cfg.dynamicSmemBytes = 0;
    cfg.stream = 0;
    cudaLaunchAttribute attr[1];
    attr[0].id = cudaLaunchAttributeProgrammaticStreamSerialization;
    attr[0].val.programmaticStreamSerializationAllowed = 1;
    cfg.attrs = attr;
    cfg.numAttrs = 1;
    cudaLaunchKernelEx(&cfg, dncm_final_kernel, T, P, Q, out);
}